// round 12
// baseline (speedup 1.0000x reference)
#include <cuda_runtime.h>
#include <cuda_fp16.h>
#include <cstdint>

#define SEQ   2048
#define EMB   1024
#define NH    16
#define HD    64
#define NTOK  8192      // B*S
#define NBH   64        // B*H

// Scratch
__device__ __half g_Q[(size_t)NTOK * EMB];          // [bh][s][d]
__device__ __half g_K[(size_t)NTOK * EMB];          // [bh][s][d]
__device__ __half g_V[(size_t)NTOK * EMB];          // [bh][d][s]  (transposed)
__device__ __half g_C[(size_t)NTOK * EMB];          // [token][E]
__device__ __half g_X[(size_t)NTOK * EMB];          // fp16 x
__device__ __half g_W[(size_t)4 * EMB * EMB];       // fp16 Wq,Wk,Wv,Wo

__device__ __forceinline__ void mma16(float* d, const uint32_t* a, const uint32_t* b) {
    asm volatile(
        "mma.sync.aligned.m16n8k16.row.col.f32.f16.f16.f32 "
        "{%0,%1,%2,%3}, {%4,%5,%6,%7}, {%8,%9}, {%0,%1,%2,%3};\n"
        : "+f"(d[0]), "+f"(d[1]), "+f"(d[2]), "+f"(d[3])
        : "r"(a[0]), "r"(a[1]), "r"(a[2]), "r"(a[3]), "r"(b[0]), "r"(b[1]));
}

__device__ __forceinline__ void ldsm_x4(
    uint32_t& r0, uint32_t& r1, uint32_t& r2, uint32_t& r3, uint32_t addr)
{
    asm volatile("ldmatrix.sync.aligned.m8n8.x4.shared.b16 {%0,%1,%2,%3}, [%4];"
                 : "=r"(r0), "=r"(r1), "=r"(r2), "=r"(r3) : "r"(addr));
}

__device__ __forceinline__ uint32_t smem_u32(const void* p) {
    uint32_t a;
    asm("{ .reg .u64 t; cvta.to.shared.u64 t, %1; cvt.u32.u64 %0, t; }"
        : "=r"(a) : "l"(p));
    return a;
}

// ===========================================================================
// Convert x and all W to fp16 once.
// ===========================================================================
__global__ void round_inputs(
    const float4* __restrict__ x,
    const float4* __restrict__ wq, const float4* __restrict__ wk,
    const float4* __restrict__ wv, const float4* __restrict__ wo)
{
    const size_t NX = (size_t)NTOK * EMB / 8;
    const size_t NW = (size_t)EMB * EMB / 8;
    __half* X = g_X;
    __half* W = g_W;
    const size_t stride = (size_t)gridDim.x * blockDim.x;
    for (size_t g = (size_t)blockIdx.x * blockDim.x + threadIdx.x;
         g < NX + 4 * NW; g += stride) {
        const float4* s; __half* d;
        if (g < NX) { s = x + 2 * g; d = X + 8 * g; }
        else {
            size_t j = g - NX;
            int w = (int)(j / NW);
            size_t o = j % NW;
            const float4* ws = (w == 0) ? wq : (w == 1) ? wk : (w == 2) ? wv : wo;
            s = ws + 2 * o; d = W + (size_t)w * NW * 8 + 8 * o;
        }
        float4 v0 = s[0], v1 = s[1];
        __half h[8];
        h[0] = __float2half_rn(v0.x); h[1] = __float2half_rn(v0.y);
        h[2] = __float2half_rn(v0.z); h[3] = __float2half_rn(v0.w);
        h[4] = __float2half_rn(v1.x); h[5] = __float2half_rn(v1.y);
        h[6] = __float2half_rn(v1.z); h[7] = __float2half_rn(v1.w);
        *(uint4*)d = *(uint4*)h;
    }
}

// ===========================================================================
// FP16 GEMM (mma m16n8k16 + ldmatrix) — unchanged from R9 (proven).
// ===========================================================================
#define G_STRW 20
#define G_TILEW (128 * G_STRW)

struct GemmSmem {
    uint32_t As[2][G_TILEW];
    uint32_t Bs[2][G_TILEW];
};

__device__ __forceinline__ void g_stage(
    uint32_t* As, uint32_t* Bs,
    const uint4& a0, const uint4& a1, const uint4& w0, const uint4& w1,
    int lrow, int c)
{
    *(uint4*)&As[lrow * G_STRW + c * 4]        = a0;
    *(uint4*)&As[(lrow + 64) * G_STRW + c * 4] = a1;
    *(uint4*)&Bs[lrow * G_STRW + c * 4]        = w0;
    *(uint4*)&Bs[(lrow + 64) * G_STRW + c * 4] = w1;
}

__device__ __forceinline__ void g_compute(
    uint32_t a0b, uint32_t b0b, float acc[4][4][4])
{
#pragma unroll
    for (int ks = 0; ks < 2; ks++) {
        uint32_t af[4][4], bf[4][2];
#pragma unroll
        for (int mt = 0; mt < 4; mt++)
            ldsm_x4(af[mt][0], af[mt][1], af[mt][2], af[mt][3],
                    a0b + mt * (16 * G_STRW * 4) + ks * 32);
#pragma unroll
        for (int n2 = 0; n2 < 2; n2++) {
            uint32_t r0, r1, r2, r3;
            ldsm_x4(r0, r1, r2, r3, b0b + n2 * (16 * G_STRW * 4) + ks * 32);
            bf[2*n2][0] = r0; bf[2*n2+1][0] = r1;
            bf[2*n2][1] = r2; bf[2*n2+1][1] = r3;
        }
#pragma unroll
        for (int mt = 0; mt < 4; mt++)
#pragma unroll
            for (int nt = 0; nt < 4; nt++)
                mma16(acc[mt][nt], af[mt], bf[nt]);
    }
}

// OUT_MODE: 0 = fp32 [token][E], 1 = half [bh][s][d] (Q,K), 2 = half [bh][d][s] (V)
template<int OUT_MODE, typename OutT>
__device__ __forceinline__ void gemm_body(
    const __half* __restrict__ A, const __half* __restrict__ W,
    const float* __restrict__ bias, OutT* __restrict__ Cout, GemmSmem& S)
{
    const int tid  = threadIdx.x;
    const int bm   = blockIdx.y * 128;
    const int bn   = blockIdx.x * 128;
    const int lrow = tid >> 2;
    const int c    = tid & 3;
    const int warp = tid >> 5, lane = tid & 31;
    const int wm = warp >> 2, wn = warp & 3;
    const int gid = lane >> 2, tq = lane & 3;

    const __half* A0 = A + (size_t)(bm + lrow) * EMB + c * 8;
    const __half* A1 = A0 + (size_t)64 * EMB;
    const __half* W0 = W + (size_t)(bn + lrow) * EMB + c * 8;
    const __half* W1 = W0 + (size_t)64 * EMB;

    const int l16 = lane & 15;
    const int lhw = (lane >> 4) * 4;
    const uint32_t aoff = (uint32_t)(((wm * 64 + l16) * G_STRW + lhw) * 4);
    const uint32_t boff = (uint32_t)(((wn * 32 + l16) * G_STRW + lhw) * 4);
    const uint32_t ab[2] = { smem_u32(&S.As[0][0]) + aoff, smem_u32(&S.As[1][0]) + aoff };
    const uint32_t bb[2] = { smem_u32(&S.Bs[0][0]) + boff, smem_u32(&S.Bs[1][0]) + boff };

    float acc[4][4][4];
#pragma unroll
    for (int i = 0; i < 4; i++)
#pragma unroll
        for (int j = 0; j < 4; j++)
#pragma unroll
            for (int v = 0; v < 4; v++) acc[i][j][v] = 0.f;

    uint4 a0 = *(const uint4*)(A0);
    uint4 a1 = *(const uint4*)(A1);
    uint4 w0 = *(const uint4*)(W0);
    uint4 w1 = *(const uint4*)(W1);
    g_stage(S.As[0], S.Bs[0], a0, a1, w0, w1, lrow, c);
    __syncthreads();

    int buf = 0;
#pragma unroll 1
    for (int k0 = 32; k0 < EMB; k0 += 32) {
        a0 = *(const uint4*)(A0 + k0);
        a1 = *(const uint4*)(A1 + k0);
        w0 = *(const uint4*)(W0 + k0);
        w1 = *(const uint4*)(W1 + k0);
        g_compute(ab[buf], bb[buf], acc);
        g_stage(S.As[buf ^ 1], S.Bs[buf ^ 1], a0, a1, w0, w1, lrow, c);
        __syncthreads();
        buf ^= 1;
    }
    g_compute(ab[buf], bb[buf], acc);

#pragma unroll
    for (int mt = 0; mt < 4; mt++) {
#pragma unroll
        for (int nt = 0; nt < 4; nt++) {
            const int m_ = bm + wm * 64 + mt * 16 + gid;
            const int n_ = bn + wn * 32 + nt * 8 + 2 * tq;
            const float bz0 = bias[n_], bz1 = bias[n_ + 1];
            const float c00 = acc[mt][nt][0] + bz0;
            const float c01 = acc[mt][nt][1] + bz1;
            const float c10 = acc[mt][nt][2] + bz0;
            const float c11 = acc[mt][nt][3] + bz1;
            if (OUT_MODE == 0) {
                float* o = (float*)Cout;
                *(float2*)&o[(size_t)m_ * EMB + n_]       = make_float2(c00, c01);
                *(float2*)&o[(size_t)(m_ + 8) * EMB + n_] = make_float2(c10, c11);
            } else if (OUT_MODE == 1) {
                __half* o = (__half*)Cout;
                const int b = m_ >> 11, s = m_ & (SEQ - 1);
                const int h = n_ >> 6,  d = n_ & 63;
                *(__half2*)&o[((size_t)(b*NH+h)*SEQ + s) * HD + d] =
                    __floats2half2_rn(c00, c01);
                *(__half2*)&o[((size_t)(b*NH+h)*SEQ + s + 8) * HD + d] =
                    __floats2half2_rn(c10, c11);
            } else {
                __half* o = (__half*)Cout;
                const int b = m_ >> 11, s = m_ & (SEQ - 1);
                const int h = n_ >> 6,  d = n_ & 63;
                const size_t base = ((size_t)(b*NH+h)*HD + d) * SEQ;
                o[base + s]            = __float2half_rn(c00);
                o[base + SEQ + s]      = __float2half_rn(c01);
                o[base + s + 8]        = __float2half_rn(c10);
                o[base + SEQ + s + 8]  = __float2half_rn(c11);
            }
        }
    }
}

__global__ void __launch_bounds__(256, 2) gemm_qkv(
    const __half* __restrict__ A, const __half* __restrict__ Wcat,
    const float* __restrict__ bq, const float* __restrict__ bk,
    const float* __restrict__ bv,
    __half* __restrict__ Qo, __half* __restrict__ Ko, __half* __restrict__ Vo)
{
    __shared__ GemmSmem S;
    const int z = blockIdx.z;
    const __half* W = Wcat + (size_t)z * EMB * EMB;
    if (z == 0)      gemm_body<1>(A, W, bq, Qo, S);
    else if (z == 1) gemm_body<1>(A, W, bk, Ko, S);
    else             gemm_body<2>(A, W, bv, Vo, S);
}

__global__ void __launch_bounds__(256, 2) gemm_o(
    const __half* __restrict__ A, const __half* __restrict__ W,
    const float* __restrict__ bias, float* __restrict__ out)
{
    __shared__ GemmSmem S;
    gemm_body<0>(A, W, bias, out, S);
}

// ===========================================================================
// Fused attention, fp16 mma + ldmatrix, 512 threads.
// R10: Q fragments hoisted to registers; V and P double-buffered ->
//      ONE __syncthreads() per key tile (was 2).
//   Qs [128][32w]   Ks[2][128][32w]   Vt[2][64][64w]   Ps[2][128][64w]
// ===========================================================================
#define AQ_OFF 0
#define AK_OFF (128 * 32)                    // 4096
#define AV_OFF (AK_OFF + 2 * 128 * 32)       // 12288
#define AP_OFF (AV_OFF + 2 * 64 * 64)        // 20480
#define A_SMEM_WORDS (AP_OFF + 2 * 128 * 64) // 36864 words = 144KB

__device__ __forceinline__ int swz32(int row, int w) {
    return row * 32 + (w ^ ((row & 7) << 2));
}
__device__ __forceinline__ int swz64(int row, int w) {
    return row * 64 + (w ^ ((row & 7) << 2));
}
__device__ __forceinline__ uint32_t a32(uint32_t base_b, int row, int w) {
    return base_b + row * 128 + (uint32_t)((w ^ ((row & 7) << 2)) << 2);
}
__device__ __forceinline__ uint32_t a64(uint32_t base_b, int row, int w) {
    return base_b + row * 256 + (uint32_t)((w ^ ((row & 7) << 2)) << 2);
}

__global__ void __launch_bounds__(512, 1) attn_f16(
    const __half* __restrict__ Q, const __half* __restrict__ K,
    const __half* __restrict__ V, __half* __restrict__ Cctx)
{
    extern __shared__ uint32_t sm[];
    const uint32_t smb = smem_u32(sm);

    const int tid  = threadIdx.x;
    const int warp = tid >> 5, lane = tid & 31;
    const int gid  = lane >> 2, tq = lane & 3;
    const int wm1 = warp >> 2, wn1 = warp & 3;    // gemm1: 4x4, warp 32x32
    const int wm2 = warp >> 1, wn2 = warp & 1;    // gemm2: 8x2, warp 16x32
    const int bh = blockIdx.y;
    const int q0 = blockIdx.x * 128;

    const __half* Qbh = Q + (size_t)bh * SEQ * HD;
    const __half* Kbh = K + (size_t)bh * SEQ * HD;
    const __half* Vbh = V + (size_t)bh * HD * SEQ;

    const int l16 = lane & 15;
    const int lhw = (lane >> 4) * 4;

    int qkr[2], qkc[2], vr[2], vc[2];
#pragma unroll
    for (int p = 0; p < 2; p++) {
        const int idx = tid + (p << 9);
        qkr[p] = idx >> 3;  qkc[p] = idx & 7;
        vr[p]  = idx >> 4;  vc[p]  = idx & 15;
    }

    // prologue: Q, K0 -> Kbuf0, V0 -> Vbuf0
#pragma unroll
    for (int p = 0; p < 2; p++) {
        const uint4 qv = *(const uint4*)(Qbh + (size_t)(q0 + qkr[p]) * HD + qkc[p] * 8);
        const uint4 kv = *(const uint4*)(Kbh + (size_t)qkr[p] * HD + qkc[p] * 8);
        const uint4 vv = *(const uint4*)(Vbh + (size_t)vr[p] * SEQ + vc[p] * 8);
        *(uint4*)&sm[AQ_OFF + swz32(qkr[p], 4 * qkc[p])] = qv;
        *(uint4*)&sm[AK_OFF + swz32(qkr[p], 4 * qkc[p])] = kv;
        *(uint4*)&sm[AV_OFF + swz64(vr[p],  4 * vc[p])]  = vv;
    }
    __syncthreads();

    // hoist Q fragments (invariant across all key tiles)
    uint32_t qf[2][4][4];
#pragma unroll
    for (int mt = 0; mt < 2; mt++)
#pragma unroll
        for (int ks = 0; ks < 4; ks++)
            ldsm_x4(qf[mt][ks][0], qf[mt][ks][1], qf[mt][ks][2], qf[mt][ks][3],
                    a32(smb + AQ_OFF * 4, wm1 * 32 + mt * 16 + l16, ks * 8 + lhw));

    float acc2[4][4];
#pragma unroll
    for (int j = 0; j < 4; j++)
#pragma unroll
        for (int v = 0; v < 4; v++) acc2[j][v] = 0.f;

#pragma unroll 1
    for (int kt = 0; kt < 16; kt++) {
        const int nk = (kt + 1 < 16) ? (kt + 1) : 15;

        uint4 kreg[2], vreg[2];
#pragma unroll
        for (int p = 0; p < 2; p++) {
            kreg[p] = *(const uint4*)(Kbh + (size_t)(nk * 128 + qkr[p]) * HD + qkc[p] * 8);
            vreg[p] = *(const uint4*)(Vbh + (size_t)vr[p] * SEQ + nk * 128 + vc[p] * 8);
        }

        const uint32_t ks_base = smb + (AK_OFF + (kt & 1) * (128 * 32)) * 4;
        const uint32_t vs_base = smb + (AV_OFF + (kt & 1) * (64 * 64)) * 4;
        const uint32_t ps_base = smb + (AP_OFF + (kt & 1) * (128 * 64)) * 4;
        uint32_t* Ps = sm + AP_OFF + (kt & 1) * (128 * 64);

        // gemm1: S[i][j] = sum_d Q[i][d] K[j][d]
        float acc1[2][4][4];
#pragma unroll
        for (int i = 0; i < 2; i++)
#pragma unroll
            for (int j = 0; j < 4; j++)
#pragma unroll
                for (int v = 0; v < 4; v++) acc1[i][j][v] = 0.f;

#pragma unroll
        for (int ks = 0; ks < 4; ks++) {
            const int w = ks * 8 + lhw;
            uint32_t bf[4][2];
#pragma unroll
            for (int n2 = 0; n2 < 2; n2++) {
                const int row = wn1 * 32 + n2 * 16 + l16;
                uint32_t r0, r1, r2, r3;
                ldsm_x4(r0, r1, r2, r3, a32(ks_base, row, w));
                bf[2*n2][0] = r0; bf[2*n2+1][0] = r1;
                bf[2*n2][1] = r2; bf[2*n2+1][1] = r3;
            }
#pragma unroll
            for (int mt = 0; mt < 2; mt++)
#pragma unroll
                for (int nt = 0; nt < 4; nt++)
                    mma16(acc1[mt][nt], qf[mt][ks], bf[nt]);
        }

        // STS K(kt+1) into the other K buffer (nobody reads it now)
        {
            uint32_t* Kn = sm + AK_OFF + ((kt + 1) & 1) * (128 * 32);
#pragma unroll
            for (int p = 0; p < 2; p++)
                *(uint4*)&Kn[swz32(qkr[p], 4 * qkc[p])] = kreg[p];
        }

        // softsign (1/8 folded) -> Ps[kt&1]
#pragma unroll
        for (int mt = 0; mt < 2; mt++) {
#pragma unroll
            for (int nt = 0; nt < 4; nt++) {
                const int row = wm1 * 32 + mt * 16 + gid;
                const int cw  = wn1 * 16 + nt * 4 + tq;
                const float s0 = acc1[mt][nt][0], s1 = acc1[mt][nt][1];
                const float s2 = acc1[mt][nt][2], s3 = acc1[mt][nt][3];
                *(__half2*)&Ps[swz64(row, cw)] =
                    __floats2half2_rn(__fdividef(s0, 8.f + fabsf(s0)),
                                      __fdividef(s1, 8.f + fabsf(s1)));
                *(__half2*)&Ps[swz64(row + 8, cw)] =
                    __floats2half2_rn(__fdividef(s2, 8.f + fabsf(s2)),
                                      __fdividef(s3, 8.f + fabsf(s3)));
            }
        }
        __syncthreads();   // single barrier per tile

        // STS V(kt+1) into the other V buffer (gemm2(kt-1) readers of this
        // buffer provably finished before anyone passed the barrier above)
        {
            uint32_t* Vn = sm + AV_OFF + ((kt + 1) & 1) * (64 * 64);
#pragma unroll
            for (int p = 0; p < 2; p++)
                *(uint4*)&Vn[swz64(vr[p], 4 * vc[p])] = vreg[p];
        }

        // gemm2: ctx[i][d] += sum_j P[i][j] V[j][d]
#pragma unroll
        for (int ks = 0; ks < 8; ks++) {
            const int w = ks * 8 + lhw;
            uint32_t af[4], bf[4][2];
            {
                const int row = wm2 * 16 + l16;
                ldsm_x4(af[0], af[1], af[2], af[3], a64(ps_base, row, w));
            }
#pragma unroll
            for (int n2 = 0; n2 < 2; n2++) {
                const int row = wn2 * 32 + n2 * 16 + l16;
                uint32_t r0, r1, r2, r3;
                ldsm_x4(r0, r1, r2, r3, a64(vs_base, row, w));
                bf[2*n2][0] = r0; bf[2*n2+1][0] = r1;
                bf[2*n2][1] = r2; bf[2*n2+1][1] = r3;
            }
#pragma unroll
            for (int nt = 0; nt < 4; nt++)
                mma16(acc2[nt], af, bf[nt]);
        }
    }

    // epilogue: ctx -> half [token][E]
    const int b = bh >> 4, h = bh & 15;
#pragma unroll
    for (int nt = 0; nt < 4; nt++) {
        const int i = wm2 * 16 + gid;
        const int d = wn2 * 32 + nt * 8 + 2 * tq;
        __half* o0 = &Cctx[(size_t)(b * SEQ + q0 + i    ) * EMB + h * HD + d];
        __half* o1 = &Cctx[(size_t)(b * SEQ + q0 + i + 8) * EMB + h * HD + d];
        *(__half2*)o0 = __floats2half2_rn(acc2[nt][0], acc2[nt][1]);
        *(__half2*)o1 = __floats2half2_rn(acc2[nt][2], acc2[nt][3]);
    }
}

// ===========================================================================
extern "C" void kernel_launch(void* const* d_in, const int* in_sizes, int n_in,
                              void* d_out, int out_size)
{
    (void)in_sizes; (void)n_in; (void)out_size;
    const float* x  = (const float*)d_in[0];
    const float* Wq = (const float*)d_in[1];
    const float* bq = (const float*)d_in[2];
    const float* Wk = (const float*)d_in[3];
    const float* bk = (const float*)d_in[4];
    const float* Wv = (const float*)d_in[5];
    const float* bv = (const float*)d_in[6];
    const float* Wo = (const float*)d_in[7];
    const float* bo = (const float*)d_in[8];
    float* out = (float*)d_out;

    __half *Qp, *Kp, *Vp, *Cp, *Xp, *Wp;
    cudaGetSymbolAddress((void**)&Qp, g_Q);
    cudaGetSymbolAddress((void**)&Kp, g_K);
    cudaGetSymbolAddress((void**)&Vp, g_V);
    cudaGetSymbolAddress((void**)&Cp, g_C);
    cudaGetSymbolAddress((void**)&Xp, g_X);
    cudaGetSymbolAddress((void**)&Wp, g_W);

    round_inputs<<<2048, 256>>>((const float4*)x, (const float4*)Wq,
                                (const float4*)Wk, (const float4*)Wv,
                                (const float4*)Wo);

    gemm_qkv<<<dim3(EMB / 128, NTOK / 128, 3), 256>>>(
        Xp, Wp, bq, bk, bv, Qp, Kp, Vp);

    const size_t attn_smem = (size_t)A_SMEM_WORDS * sizeof(uint32_t);  // 144KB
    cudaFuncSetAttribute(attn_f16, cudaFuncAttributeMaxDynamicSharedMemorySize,
                         (int)attn_smem);
    attn_f16<<<dim3(SEQ / 128, NBH), 512, attn_smem>>>(Qp, Kp, Vp, Cp);

    gemm_o<<<dim3(EMB / 128, NTOK / 128), 256>>>(
        Cp, Wp + (size_t)3 * EMB * EMB, bo, out);
}

// round 13
// speedup vs baseline: 1.0021x; 1.0021x over previous
#include <cuda_runtime.h>
#include <cuda_fp16.h>
#include <cstdint>

#define SEQ   2048
#define EMB   1024
#define NH    16
#define HD    64
#define NTOK  8192      // B*S
#define NBH   64        // B*H

// Scratch
__device__ __half g_Q[(size_t)NTOK * EMB];          // [bh][s][d]
__device__ __half g_K[(size_t)NTOK * EMB];          // [bh][s][d]
__device__ __half g_V[(size_t)NTOK * EMB];          // [bh][d][s]  (transposed)
__device__ __half g_C[(size_t)NTOK * EMB];          // [token][E]
__device__ __half g_X[(size_t)NTOK * EMB];          // fp16 x
__device__ __half g_W[(size_t)4 * EMB * EMB];       // fp16 Wq,Wk,Wv,Wo

__device__ __forceinline__ void mma16(float* d, const uint32_t* a, const uint32_t* b) {
    asm volatile(
        "mma.sync.aligned.m16n8k16.row.col.f32.f16.f16.f32 "
        "{%0,%1,%2,%3}, {%4,%5,%6,%7}, {%8,%9}, {%0,%1,%2,%3};\n"
        : "+f"(d[0]), "+f"(d[1]), "+f"(d[2]), "+f"(d[3])
        : "r"(a[0]), "r"(a[1]), "r"(a[2]), "r"(a[3]), "r"(b[0]), "r"(b[1]));
}

__device__ __forceinline__ void ldsm_x4(
    uint32_t& r0, uint32_t& r1, uint32_t& r2, uint32_t& r3, uint32_t addr)
{
    asm volatile("ldmatrix.sync.aligned.m8n8.x4.shared.b16 {%0,%1,%2,%3}, [%4];"
                 : "=r"(r0), "=r"(r1), "=r"(r2), "=r"(r3) : "r"(addr));
}

__device__ __forceinline__ uint32_t smem_u32(const void* p) {
    uint32_t a;
    asm("{ .reg .u64 t; cvta.to.shared.u64 t, %1; cvt.u32.u64 %0, t; }"
        : "=r"(a) : "l"(p));
    return a;
}

// ===========================================================================
// Convert x and all W to fp16 once.
// ===========================================================================
__global__ void round_inputs(
    const float4* __restrict__ x,
    const float4* __restrict__ wq, const float4* __restrict__ wk,
    const float4* __restrict__ wv, const float4* __restrict__ wo)
{
    const size_t NX = (size_t)NTOK * EMB / 8;
    const size_t NW = (size_t)EMB * EMB / 8;
    __half* X = g_X;
    __half* W = g_W;
    const size_t stride = (size_t)gridDim.x * blockDim.x;
    for (size_t g = (size_t)blockIdx.x * blockDim.x + threadIdx.x;
         g < NX + 4 * NW; g += stride) {
        const float4* s; __half* d;
        if (g < NX) { s = x + 2 * g; d = X + 8 * g; }
        else {
            size_t j = g - NX;
            int w = (int)(j / NW);
            size_t o = j % NW;
            const float4* ws = (w == 0) ? wq : (w == 1) ? wk : (w == 2) ? wv : wo;
            s = ws + 2 * o; d = W + (size_t)w * NW * 8 + 8 * o;
        }
        float4 v0 = s[0], v1 = s[1];
        __half h[8];
        h[0] = __float2half_rn(v0.x); h[1] = __float2half_rn(v0.y);
        h[2] = __float2half_rn(v0.z); h[3] = __float2half_rn(v0.w);
        h[4] = __float2half_rn(v1.x); h[5] = __float2half_rn(v1.y);
        h[6] = __float2half_rn(v1.z); h[7] = __float2half_rn(v1.w);
        *(uint4*)d = *(uint4*)h;
    }
}

// ===========================================================================
// FP16 GEMM (mma m16n8k16 + ldmatrix) — unchanged from R9 (proven).
// ===========================================================================
#define G_STRW 20
#define G_TILEW (128 * G_STRW)

struct GemmSmem {
    uint32_t As[2][G_TILEW];
    uint32_t Bs[2][G_TILEW];
};

__device__ __forceinline__ void g_stage(
    uint32_t* As, uint32_t* Bs,
    const uint4& a0, const uint4& a1, const uint4& w0, const uint4& w1,
    int lrow, int c)
{
    *(uint4*)&As[lrow * G_STRW + c * 4]        = a0;
    *(uint4*)&As[(lrow + 64) * G_STRW + c * 4] = a1;
    *(uint4*)&Bs[lrow * G_STRW + c * 4]        = w0;
    *(uint4*)&Bs[(lrow + 64) * G_STRW + c * 4] = w1;
}

__device__ __forceinline__ void g_compute(
    uint32_t a0b, uint32_t b0b, float acc[4][4][4])
{
#pragma unroll
    for (int ks = 0; ks < 2; ks++) {
        uint32_t af[4][4], bf[4][2];
#pragma unroll
        for (int mt = 0; mt < 4; mt++)
            ldsm_x4(af[mt][0], af[mt][1], af[mt][2], af[mt][3],
                    a0b + mt * (16 * G_STRW * 4) + ks * 32);
#pragma unroll
        for (int n2 = 0; n2 < 2; n2++) {
            uint32_t r0, r1, r2, r3;
            ldsm_x4(r0, r1, r2, r3, b0b + n2 * (16 * G_STRW * 4) + ks * 32);
            bf[2*n2][0] = r0; bf[2*n2+1][0] = r1;
            bf[2*n2][1] = r2; bf[2*n2+1][1] = r3;
        }
#pragma unroll
        for (int mt = 0; mt < 4; mt++)
#pragma unroll
            for (int nt = 0; nt < 4; nt++)
                mma16(acc[mt][nt], af[mt], bf[nt]);
    }
}

// OUT_MODE: 0 = fp32 [token][E], 1 = half [bh][s][d] (Q,K), 2 = half [bh][d][s] (V)
template<int OUT_MODE, typename OutT>
__device__ __forceinline__ void gemm_body(
    const __half* __restrict__ A, const __half* __restrict__ W,
    const float* __restrict__ bias, OutT* __restrict__ Cout, GemmSmem& S)
{
    const int tid  = threadIdx.x;
    const int bm   = blockIdx.y * 128;
    const int bn   = blockIdx.x * 128;
    const int lrow = tid >> 2;
    const int c    = tid & 3;
    const int warp = tid >> 5, lane = tid & 31;
    const int wm = warp >> 2, wn = warp & 3;
    const int gid = lane >> 2, tq = lane & 3;

    const __half* A0 = A + (size_t)(bm + lrow) * EMB + c * 8;
    const __half* A1 = A0 + (size_t)64 * EMB;
    const __half* W0 = W + (size_t)(bn + lrow) * EMB + c * 8;
    const __half* W1 = W0 + (size_t)64 * EMB;

    const int l16 = lane & 15;
    const int lhw = (lane >> 4) * 4;
    const uint32_t aoff = (uint32_t)(((wm * 64 + l16) * G_STRW + lhw) * 4);
    const uint32_t boff = (uint32_t)(((wn * 32 + l16) * G_STRW + lhw) * 4);
    const uint32_t ab[2] = { smem_u32(&S.As[0][0]) + aoff, smem_u32(&S.As[1][0]) + aoff };
    const uint32_t bb[2] = { smem_u32(&S.Bs[0][0]) + boff, smem_u32(&S.Bs[1][0]) + boff };

    float acc[4][4][4];
#pragma unroll
    for (int i = 0; i < 4; i++)
#pragma unroll
        for (int j = 0; j < 4; j++)
#pragma unroll
            for (int v = 0; v < 4; v++) acc[i][j][v] = 0.f;

    uint4 a0 = *(const uint4*)(A0);
    uint4 a1 = *(const uint4*)(A1);
    uint4 w0 = *(const uint4*)(W0);
    uint4 w1 = *(const uint4*)(W1);
    g_stage(S.As[0], S.Bs[0], a0, a1, w0, w1, lrow, c);
    __syncthreads();

    int buf = 0;
#pragma unroll 1
    for (int k0 = 32; k0 < EMB; k0 += 32) {
        a0 = *(const uint4*)(A0 + k0);
        a1 = *(const uint4*)(A1 + k0);
        w0 = *(const uint4*)(W0 + k0);
        w1 = *(const uint4*)(W1 + k0);
        g_compute(ab[buf], bb[buf], acc);
        g_stage(S.As[buf ^ 1], S.Bs[buf ^ 1], a0, a1, w0, w1, lrow, c);
        __syncthreads();
        buf ^= 1;
    }
    g_compute(ab[buf], bb[buf], acc);

#pragma unroll
    for (int mt = 0; mt < 4; mt++) {
#pragma unroll
        for (int nt = 0; nt < 4; nt++) {
            const int m_ = bm + wm * 64 + mt * 16 + gid;
            const int n_ = bn + wn * 32 + nt * 8 + 2 * tq;
            const float bz0 = bias[n_], bz1 = bias[n_ + 1];
            const float c00 = acc[mt][nt][0] + bz0;
            const float c01 = acc[mt][nt][1] + bz1;
            const float c10 = acc[mt][nt][2] + bz0;
            const float c11 = acc[mt][nt][3] + bz1;
            if (OUT_MODE == 0) {
                float* o = (float*)Cout;
                *(float2*)&o[(size_t)m_ * EMB + n_]       = make_float2(c00, c01);
                *(float2*)&o[(size_t)(m_ + 8) * EMB + n_] = make_float2(c10, c11);
            } else if (OUT_MODE == 1) {
                __half* o = (__half*)Cout;
                const int b = m_ >> 11, s = m_ & (SEQ - 1);
                const int h = n_ >> 6,  d = n_ & 63;
                *(__half2*)&o[((size_t)(b*NH+h)*SEQ + s) * HD + d] =
                    __floats2half2_rn(c00, c01);
                *(__half2*)&o[((size_t)(b*NH+h)*SEQ + s + 8) * HD + d] =
                    __floats2half2_rn(c10, c11);
            } else {
                __half* o = (__half*)Cout;
                const int b = m_ >> 11, s = m_ & (SEQ - 1);
                const int h = n_ >> 6,  d = n_ & 63;
                const size_t base = ((size_t)(b*NH+h)*HD + d) * SEQ;
                o[base + s]            = __float2half_rn(c00);
                o[base + SEQ + s]      = __float2half_rn(c01);
                o[base + s + 8]        = __float2half_rn(c10);
                o[base + SEQ + s + 8]  = __float2half_rn(c11);
            }
        }
    }
}

__global__ void __launch_bounds__(256, 2) gemm_qkv(
    const __half* __restrict__ A, const __half* __restrict__ Wcat,
    const float* __restrict__ bq, const float* __restrict__ bk,
    const float* __restrict__ bv,
    __half* __restrict__ Qo, __half* __restrict__ Ko, __half* __restrict__ Vo)
{
    __shared__ GemmSmem S;
    const int z = blockIdx.z;
    const __half* W = Wcat + (size_t)z * EMB * EMB;
    if (z == 0)      gemm_body<1>(A, W, bq, Qo, S);
    else if (z == 1) gemm_body<1>(A, W, bk, Ko, S);
    else             gemm_body<2>(A, W, bv, Vo, S);
}

__global__ void __launch_bounds__(256, 2) gemm_o(
    const __half* __restrict__ A, const __half* __restrict__ W,
    const float* __restrict__ bias, float* __restrict__ out)
{
    __shared__ GemmSmem S;
    gemm_body<0>(A, W, bias, out, S);
}

// ===========================================================================
// Fused attention, fp16 mma + ldmatrix, 512 threads.
// R10: Q fragments hoisted to registers; V and P double-buffered ->
//      ONE __syncthreads() per key tile (was 2).
//   Qs [128][32w]   Ks[2][128][32w]   Vt[2][64][64w]   Ps[2][128][64w]
// ===========================================================================
#define AQ_OFF 0
#define AK_OFF (128 * 32)                    // 4096
#define AV_OFF (AK_OFF + 2 * 128 * 32)       // 12288
#define AP_OFF (AV_OFF + 2 * 64 * 64)        // 20480
#define A_SMEM_WORDS (AP_OFF + 2 * 128 * 64) // 36864 words = 144KB

__device__ __forceinline__ int swz32(int row, int w) {
    return row * 32 + (w ^ ((row & 7) << 2));
}
__device__ __forceinline__ int swz64(int row, int w) {
    return row * 64 + (w ^ ((row & 7) << 2));
}
__device__ __forceinline__ uint32_t a32(uint32_t base_b, int row, int w) {
    return base_b + row * 128 + (uint32_t)((w ^ ((row & 7) << 2)) << 2);
}
__device__ __forceinline__ uint32_t a64(uint32_t base_b, int row, int w) {
    return base_b + row * 256 + (uint32_t)((w ^ ((row & 7) << 2)) << 2);
}

__global__ void __launch_bounds__(512, 1) attn_f16(
    const __half* __restrict__ Q, const __half* __restrict__ K,
    const __half* __restrict__ V, __half* __restrict__ Cctx)
{
    extern __shared__ uint32_t sm[];
    const uint32_t smb = smem_u32(sm);

    const int tid  = threadIdx.x;
    const int warp = tid >> 5, lane = tid & 31;
    const int gid  = lane >> 2, tq = lane & 3;
    const int wm1 = warp >> 2, wn1 = warp & 3;    // gemm1: 4x4, warp 32x32
    const int wm2 = warp >> 1, wn2 = warp & 1;    // gemm2: 8x2, warp 16x32
    const int bh = blockIdx.y;
    const int q0 = blockIdx.x * 128;

    const __half* Qbh = Q + (size_t)bh * SEQ * HD;
    const __half* Kbh = K + (size_t)bh * SEQ * HD;
    const __half* Vbh = V + (size_t)bh * HD * SEQ;

    const int l16 = lane & 15;
    const int lhw = (lane >> 4) * 4;

    int qkr[2], qkc[2], vr[2], vc[2];
#pragma unroll
    for (int p = 0; p < 2; p++) {
        const int idx = tid + (p << 9);
        qkr[p] = idx >> 3;  qkc[p] = idx & 7;
        vr[p]  = idx >> 4;  vc[p]  = idx & 15;
    }

    // prologue: Q, K0 -> Kbuf0, V0 -> Vbuf0
#pragma unroll
    for (int p = 0; p < 2; p++) {
        const uint4 qv = *(const uint4*)(Qbh + (size_t)(q0 + qkr[p]) * HD + qkc[p] * 8);
        const uint4 kv = *(const uint4*)(Kbh + (size_t)qkr[p] * HD + qkc[p] * 8);
        const uint4 vv = *(const uint4*)(Vbh + (size_t)vr[p] * SEQ + vc[p] * 8);
        *(uint4*)&sm[AQ_OFF + swz32(qkr[p], 4 * qkc[p])] = qv;
        *(uint4*)&sm[AK_OFF + swz32(qkr[p], 4 * qkc[p])] = kv;
        *(uint4*)&sm[AV_OFF + swz64(vr[p],  4 * vc[p])]  = vv;
    }
    __syncthreads();

    // hoist Q fragments (invariant across all key tiles)
    uint32_t qf[2][4][4];
#pragma unroll
    for (int mt = 0; mt < 2; mt++)
#pragma unroll
        for (int ks = 0; ks < 4; ks++)
            ldsm_x4(qf[mt][ks][0], qf[mt][ks][1], qf[mt][ks][2], qf[mt][ks][3],
                    a32(smb + AQ_OFF * 4, wm1 * 32 + mt * 16 + l16, ks * 8 + lhw));

    float acc2[4][4];
#pragma unroll
    for (int j = 0; j < 4; j++)
#pragma unroll
        for (int v = 0; v < 4; v++) acc2[j][v] = 0.f;

#pragma unroll 1
    for (int kt = 0; kt < 16; kt++) {
        const int nk = (kt + 1 < 16) ? (kt + 1) : 15;

        uint4 kreg[2], vreg[2];
#pragma unroll
        for (int p = 0; p < 2; p++) {
            kreg[p] = *(const uint4*)(Kbh + (size_t)(nk * 128 + qkr[p]) * HD + qkc[p] * 8);
            vreg[p] = *(const uint4*)(Vbh + (size_t)vr[p] * SEQ + nk * 128 + vc[p] * 8);
        }

        const uint32_t ks_base = smb + (AK_OFF + (kt & 1) * (128 * 32)) * 4;
        const uint32_t vs_base = smb + (AV_OFF + (kt & 1) * (64 * 64)) * 4;
        const uint32_t ps_base = smb + (AP_OFF + (kt & 1) * (128 * 64)) * 4;
        uint32_t* Ps = sm + AP_OFF + (kt & 1) * (128 * 64);

        // gemm1: S[i][j] = sum_d Q[i][d] K[j][d]
        float acc1[2][4][4];
#pragma unroll
        for (int i = 0; i < 2; i++)
#pragma unroll
            for (int j = 0; j < 4; j++)
#pragma unroll
                for (int v = 0; v < 4; v++) acc1[i][j][v] = 0.f;

#pragma unroll
        for (int ks = 0; ks < 4; ks++) {
            const int w = ks * 8 + lhw;
            uint32_t bf[4][2];
#pragma unroll
            for (int n2 = 0; n2 < 2; n2++) {
                const int row = wn1 * 32 + n2 * 16 + l16;
                uint32_t r0, r1, r2, r3;
                ldsm_x4(r0, r1, r2, r3, a32(ks_base, row, w));
                bf[2*n2][0] = r0; bf[2*n2+1][0] = r1;
                bf[2*n2][1] = r2; bf[2*n2+1][1] = r3;
            }
#pragma unroll
            for (int mt = 0; mt < 2; mt++)
#pragma unroll
                for (int nt = 0; nt < 4; nt++)
                    mma16(acc1[mt][nt], qf[mt][ks], bf[nt]);
        }

        // STS K(kt+1) into the other K buffer (nobody reads it now)
        {
            uint32_t* Kn = sm + AK_OFF + ((kt + 1) & 1) * (128 * 32);
#pragma unroll
            for (int p = 0; p < 2; p++)
                *(uint4*)&Kn[swz32(qkr[p], 4 * qkc[p])] = kreg[p];
        }

        // softsign (1/8 folded) -> Ps[kt&1]
#pragma unroll
        for (int mt = 0; mt < 2; mt++) {
#pragma unroll
            for (int nt = 0; nt < 4; nt++) {
                const int row = wm1 * 32 + mt * 16 + gid;
                const int cw  = wn1 * 16 + nt * 4 + tq;
                const float s0 = acc1[mt][nt][0], s1 = acc1[mt][nt][1];
                const float s2 = acc1[mt][nt][2], s3 = acc1[mt][nt][3];
                *(__half2*)&Ps[swz64(row, cw)] =
                    __floats2half2_rn(__fdividef(s0, 8.f + fabsf(s0)),
                                      __fdividef(s1, 8.f + fabsf(s1)));
                *(__half2*)&Ps[swz64(row + 8, cw)] =
                    __floats2half2_rn(__fdividef(s2, 8.f + fabsf(s2)),
                                      __fdividef(s3, 8.f + fabsf(s3)));
            }
        }
        __syncthreads();   // single barrier per tile

        // STS V(kt+1) into the other V buffer (gemm2(kt-1) readers of this
        // buffer provably finished before anyone passed the barrier above)
        {
            uint32_t* Vn = sm + AV_OFF + ((kt + 1) & 1) * (64 * 64);
#pragma unroll
            for (int p = 0; p < 2; p++)
                *(uint4*)&Vn[swz64(vr[p], 4 * vc[p])] = vreg[p];
        }

        // gemm2: ctx[i][d] += sum_j P[i][j] V[j][d]
#pragma unroll
        for (int ks = 0; ks < 8; ks++) {
            const int w = ks * 8 + lhw;
            uint32_t af[4], bf[4][2];
            {
                const int row = wm2 * 16 + l16;
                ldsm_x4(af[0], af[1], af[2], af[3], a64(ps_base, row, w));
            }
#pragma unroll
            for (int n2 = 0; n2 < 2; n2++) {
                const int row = wn2 * 32 + n2 * 16 + l16;
                uint32_t r0, r1, r2, r3;
                ldsm_x4(r0, r1, r2, r3, a64(vs_base, row, w));
                bf[2*n2][0] = r0; bf[2*n2+1][0] = r1;
                bf[2*n2][1] = r2; bf[2*n2+1][1] = r3;
            }
#pragma unroll
            for (int nt = 0; nt < 4; nt++)
                mma16(acc2[nt], af, bf[nt]);
        }
    }

    // epilogue: ctx -> half [token][E]
    const int b = bh >> 4, h = bh & 15;
#pragma unroll
    for (int nt = 0; nt < 4; nt++) {
        const int i = wm2 * 16 + gid;
        const int d = wn2 * 32 + nt * 8 + 2 * tq;
        __half* o0 = &Cctx[(size_t)(b * SEQ + q0 + i    ) * EMB + h * HD + d];
        __half* o1 = &Cctx[(size_t)(b * SEQ + q0 + i + 8) * EMB + h * HD + d];
        *(__half2*)o0 = __floats2half2_rn(acc2[nt][0], acc2[nt][1]);
        *(__half2*)o1 = __floats2half2_rn(acc2[nt][2], acc2[nt][3]);
    }
}

// ===========================================================================
extern "C" void kernel_launch(void* const* d_in, const int* in_sizes, int n_in,
                              void* d_out, int out_size)
{
    (void)in_sizes; (void)n_in; (void)out_size;
    const float* x  = (const float*)d_in[0];
    const float* Wq = (const float*)d_in[1];
    const float* bq = (const float*)d_in[2];
    const float* Wk = (const float*)d_in[3];
    const float* bk = (const float*)d_in[4];
    const float* Wv = (const float*)d_in[5];
    const float* bv = (const float*)d_in[6];
    const float* Wo = (const float*)d_in[7];
    const float* bo = (const float*)d_in[8];
    float* out = (float*)d_out;

    __half *Qp, *Kp, *Vp, *Cp, *Xp, *Wp;
    cudaGetSymbolAddress((void**)&Qp, g_Q);
    cudaGetSymbolAddress((void**)&Kp, g_K);
    cudaGetSymbolAddress((void**)&Vp, g_V);
    cudaGetSymbolAddress((void**)&Cp, g_C);
    cudaGetSymbolAddress((void**)&Xp, g_X);
    cudaGetSymbolAddress((void**)&Wp, g_W);

    round_inputs<<<2048, 256>>>((const float4*)x, (const float4*)Wq,
                                (const float4*)Wk, (const float4*)Wv,
                                (const float4*)Wo);

    gemm_qkv<<<dim3(EMB / 128, NTOK / 128, 3), 256>>>(
        Xp, Wp, bq, bk, bv, Qp, Kp, Vp);

    const size_t attn_smem = (size_t)A_SMEM_WORDS * sizeof(uint32_t);  // 144KB
    cudaFuncSetAttribute(attn_f16, cudaFuncAttributeMaxDynamicSharedMemorySize,
                         (int)attn_smem);
    attn_f16<<<dim3(SEQ / 128, NBH), 512, attn_smem>>>(Qp, Kp, Vp, Cp);

    gemm_o<<<dim3(EMB / 128, NTOK / 128), 256>>>(
        Cp, Wp + (size_t)3 * EMB * EMB, bo, out);
}